// round 1
// baseline (speedup 1.0000x reference)
#include <cuda_runtime.h>

#define NEGV (-9e15f)

// 8 precomputed scalar contractions:
// [0]=W·a1  [1]=W·a2  [2]=WS·aS1  [3]=WS·aS2
// [4]=A0=WQ0·WK0/4 [5]=B0=WQ1·WK0/4 [6]=A1=WQ0·WK1/4 [7]=B1=WQ1·WK1/4
__device__ float g_c[8];

__global__ void prep_kernel(const float* __restrict__ W,  const float* __restrict__ a,
                            const float* __restrict__ WS, const float* __restrict__ aS,
                            const float* __restrict__ WQ, const float* __restrict__ WK) {
    int l = threadIdx.x;                       // 32 threads
    float v[8];
    v[0] = W[l]*a[l]       + W[l+32]*a[l+32];
    v[1] = W[l]*a[64+l]    + W[l+32]*a[96+l];
    v[2] = WS[l]*aS[l]     + WS[l+32]*aS[l+32];
    v[3] = WS[l]*aS[64+l]  + WS[l+32]*aS[96+l];
    bool lo = (l < 16);
    v[4] = lo ? WQ[l]   *WK[l]    : 0.f;       // WQ[0,:]·WK[0,:]
    v[5] = lo ? WQ[16+l]*WK[l]    : 0.f;       // WQ[1,:]·WK[0,:]
    v[6] = lo ? WQ[l]   *WK[16+l] : 0.f;       // WQ[0,:]·WK[1,:]
    v[7] = lo ? WQ[16+l]*WK[16+l] : 0.f;       // WQ[1,:]·WK[1,:]
    #pragma unroll
    for (int k = 0; k < 8; k++)
        #pragma unroll
        for (int o = 16; o; o >>= 1) v[k] += __shfl_xor_sync(0xffffffffu, v[k], o);
    if (l == 0) {
        g_c[0] = v[0]; g_c[1] = v[1]; g_c[2] = v[2]; g_c[3] = v[3];
        g_c[4] = v[4]*0.25f; g_c[5] = v[5]*0.25f;   // /sqrt(D), D=16
        g_c[6] = v[6]*0.25f; g_c[7] = v[7]*0.25f;
    }
}

constexpr int N  = 512;
constexpr int F  = 64;
constexpr int BS = 8;
constexpr int THREADS = 256;

__global__ __launch_bounds__(THREADS)
void gat_kernel(const float* __restrict__ x,    // input  [8,512,1]
                const int*   __restrict__ adj,  // [512,512]
                const float* __restrict__ ext,  // [8,512,8]
                const float* __restrict__ side, // [8,512,1]
                const float* __restrict__ W,    // [1,64]
                const float* __restrict__ WV,   // [1,64]
                float* __restrict__ out)        // [2, 8,512,64]
{
    __shared__ float s_logit[N];
    __shared__ float s_x[N];
    __shared__ float s_red[8];
    __shared__ float s_sum[3][8];
    __shared__ float s_bcast[3];

    const int row = blockIdx.x;          // b*512 + i
    const int b   = row >> 9;
    const int i   = row & 511;
    const int tid = threadIdx.x;

    const float c1 = g_c[0], c2 = g_c[1], cs1 = g_c[2], cs2 = g_c[3];
    const float A0 = g_c[4], B0 = g_c[5], A1  = g_c[6], B1  = g_c[7];

    const float xi = x[row];
    const float si = side[row];
    float ei[8];
    {
        const float4* e4 = (const float4*)(ext + (size_t)row * 8);
        float4 ea = e4[0], eb = e4[1];
        ei[0]=ea.x; ei[1]=ea.y; ei[2]=ea.z; ei[3]=ea.w;
        ei[4]=eb.x; ei[5]=eb.y; ei[6]=eb.z; ei[7]=eb.w;
    }
    const float t1 = xi * c1;
    const float t2 = si * cs1;

    // ---- Pass A: attention logits + row max ----
    float lmax = NEGV;
    #pragma unroll
    for (int j = tid; j < N; j += THREADS) {
        float xj = x[(b << 9) + j];
        float sj = side[(b << 9) + j];
        int  aij = adj[(i << 9) + j];
        float e  = t1 + xj * c2;   e  = (e  > 0.f) ? e  : 0.2f * e;   // leakyrelu
        float es = t2 + sj * cs2;  es = (es > 0.f) ? es : 0.2f * es;
        float s  = e + es;
        float logit = (aij > 0 && s > 0.f) ? s : NEGV;
        s_logit[j] = logit;
        s_x[j]     = xj;
        lmax = fmaxf(lmax, logit);
    }
    #pragma unroll
    for (int o = 16; o; o >>= 1) lmax = fmaxf(lmax, __shfl_xor_sync(0xffffffffu, lmax, o));
    if ((tid & 31) == 0) s_red[tid >> 5] = lmax;
    __syncthreads();
    if (tid == 0) {
        float m = s_red[0];
        #pragma unroll
        for (int k = 1; k < 8; k++) m = fmaxf(m, s_red[k]);
        s_bcast[0] = m;
    }
    __syncthreads();
    const float m = s_bcast[0];

    // ---- Pass B: exp, denominator, y-numerator, z-numerator ----
    float den = 0.f, ynum = 0.f, znum = 0.f;
    #pragma unroll
    for (int j = tid; j < N; j += THREADS) {
        float p  = __expf(s_logit[j] - m);
        float xj = s_x[j];
        den  += p;
        ynum += p * xj;
        if (p != 0.f) {
            float qk0 = xi * A0 + xj * B0;
            float qk1 = xi * A1 + xj * B1;
            const float4* f4 = (const float4*)(ext + (size_t)(((b << 9) + j)) * 8);
            float4 fa = f4[0], fb = f4[1];
            float ej[8] = {fa.x, fa.y, fa.z, fa.w, fb.x, fb.y, fb.z, fb.w};
            float d[8];
            float m8 = NEGV;
            #pragma unroll
            for (int f = 0; f < 8; f++) {
                float df = ei[f] * qk0 + ej[f] * qk1;
                df = (df > 0.f) ? df : NEGV;
                d[f] = df;
                m8 = fmaxf(m8, df);
            }
            float s8 = 0.f, wn = 0.f;
            #pragma unroll
            for (int f = 0; f < 8; f++) {
                float pf = __expf(d[f] - m8);
                s8 += pf;
                wn += pf * ei[f];
            }
            znum += p * (wn / s8);
        }
    }
    #pragma unroll
    for (int o = 16; o; o >>= 1) {
        den  += __shfl_xor_sync(0xffffffffu, den,  o);
        ynum += __shfl_xor_sync(0xffffffffu, ynum, o);
        znum += __shfl_xor_sync(0xffffffffu, znum, o);
    }
    if ((tid & 31) == 0) {
        int w = tid >> 5;
        s_sum[0][w] = den; s_sum[1][w] = ynum; s_sum[2][w] = znum;
    }
    __syncthreads();
    if (tid == 0) {
        float D = 0.f, Y = 0.f, Z = 0.f;
        #pragma unroll
        for (int k = 0; k < 8; k++) { D += s_sum[0][k]; Y += s_sum[1][k]; Z += s_sum[2][k]; }
        s_bcast[1] = Y / D;
        s_bcast[2] = Z / D;
    }
    __syncthreads();
    const float y = s_bcast[1];
    const float z = s_bcast[2];

    // ---- outputs: elu(y*W[f]) and elu(z*WV[f]) ----
    if (tid < F) {
        float v1 = y * W[tid];
        v1 = (v1 > 0.f) ? v1 : expm1f(v1);
        out[(size_t)row * F + tid] = v1;
        float v2 = z * WV[tid];
        v2 = (v2 > 0.f) ? v2 : expm1f(v2);
        out[(size_t)BS * N * F + (size_t)row * F + tid] = v2;
    }
}

extern "C" void kernel_launch(void* const* d_in, const int* in_sizes, int n_in,
                              void* d_out, int out_size) {
    const float* input = (const float*)d_in[0];
    const int*   adj   = (const int*)  d_in[1];
    const float* ext   = (const float*)d_in[2];
    const float* side  = (const float*)d_in[3];
    const float* W     = (const float*)d_in[4];
    const float* a     = (const float*)d_in[5];
    const float* WS    = (const float*)d_in[6];
    const float* aS    = (const float*)d_in[7];
    const float* WQ    = (const float*)d_in[8];
    const float* WK    = (const float*)d_in[9];
    const float* WV    = (const float*)d_in[10];
    float* out = (float*)d_out;

    prep_kernel<<<1, 32>>>(W, a, WS, aS, WQ, WK);
    gat_kernel<<<BS * N, THREADS>>>(input, adj, ext, side, W, WV, out);
}